// round 16
// baseline (speedup 1.0000x reference)
#include <cuda_runtime.h>
#include <math.h>

// ---------------- problem constants ----------------
#define BATCH   32
#define CIN     256
#define COUT    64
#define HW      1024
#define NE      1024
#define EDIM    64
#define NROWS   32768
#define ZLEN    (BATCH*COUT*HW)   // 2097152
#define TILES   8
#define CODE_TILE 128
#define ROWS_BLK 112
#define RPT      7
#define NBLK     293              // argmin work units
#define GRID     296              // persistent: 148 SMs x occ 2, single wave

// output layout (concat, float32): z_q | loss | sampled | min_idx
#define ZQ_OFF   0
#define LOSS_OFF ((size_t)ZLEN)
#define SAMP_OFF ((size_t)ZLEN + 1)
#define MIDX_OFF ((size_t)ZLEN + 1 + NROWS)

// smem (union of phases): argmin layout dominates
#define ZS_F4    (ROWS_BLK * 17)          // 1904
#define ES_F4    (64 * 33)                // 2112 per buffer
#define SMEM_FUSED ((ZS_F4 + 2*ES_F4) * 16 + ROWS_BLK * 4 + 256 * 4 + 256 * 4)

// ---------------- device scratch ----------------
__device__ __align__(16) float g_z[ZLEN];
__device__ int   g_idx[NROWS];
__device__ float g_se[NE];
__device__ float g_loss_part[NBLK];
__device__ float g_s_part[32 * EDIM];
__device__ int   g_done;           // zero-init; reset by is_last each launch
__device__ int   g_norm;           // zero-init; reset by is_last
__device__ int   g_convdone[32];   // zero-init; reset by is_last

// ---------------- packed f32x2 helpers (bit-exact per-lane ops) ----------------
__device__ __forceinline__ unsigned long long dupf(float v) {
    unsigned long long r;
    asm("mov.b64 %0, {%1, %1};" : "=l"(r) : "r"(__float_as_uint(v)));
    return r;
}
__device__ __forceinline__ unsigned long long pack2(float a, float b) {
    unsigned long long r;
    asm("mov.b64 %0, {%1, %2};" : "=l"(r) : "r"(__float_as_uint(a)), "r"(__float_as_uint(b)));
    return r;
}
__device__ __forceinline__ void fma2(unsigned long long& d,
                                     unsigned long long a, unsigned long long b) {
    asm("fma.rn.f32x2 %0, %1, %2, %0;" : "+l"(d) : "l"(a), "l"(b));
}
__device__ __forceinline__ unsigned long long add2(unsigned long long a,
                                                   unsigned long long b) {
    unsigned long long d;
    asm("add.rn.f32x2 %0, %1, %2;" : "=l"(d) : "l"(a), "l"(b));
    return d;
}
__device__ __forceinline__ void unpack2(float& lo, float& hi, unsigned long long v) {
    asm("mov.b64 {%0, %1}, %2;" : "=f"(lo), "=f"(hi) : "l"(v));
}

// Replicated XLA-CPU reduce order: VF=4, IC=2, fmla, faddp-adjacent horizontal.
__device__ __forceinline__ float sumsq64_p(const float4* v4) {
    float a0=0.f,a1=0.f,a2=0.f,a3=0.f, b0=0.f,b1=0.f,b2=0.f,b3=0.f;
    #pragma unroll
    for (int t = 0; t < 8; t++) {
        float4 x = v4[2*t];
        a0 = __fmaf_rn(x.x, x.x, a0); a1 = __fmaf_rn(x.y, x.y, a1);
        a2 = __fmaf_rn(x.z, x.z, a2); a3 = __fmaf_rn(x.w, x.w, a3);
        float4 y = v4[2*t+1];
        b0 = __fmaf_rn(y.x, y.x, b0); b1 = __fmaf_rn(y.y, y.y, b1);
        b2 = __fmaf_rn(y.z, y.z, b2); b3 = __fmaf_rn(y.w, y.w, b3);
    }
    float L0 = a0 + b0, L1 = a1 + b1, L2 = a2 + b2, L3 = a3 + b3;
    return (L0 + L1) + (L2 + L3);
}

// Gather one float4 of the pair-interleaved e-tile straight from emb.
__device__ __forceinline__ float4 gather_e(const float* __restrict__ emb,
                                           int tile, int idx) {
    int pr = idx >> 5, wv = idx & 31;
    int q = pr >> 4, sl = pr & 15;
    int jlo = tile * 128 + 8 * sl + 2 * q;
    const float2* e2 = (const float2*)emb;
    float2 a = e2[jlo * 32 + wv];
    float2 b = e2[(jlo + 1) * 32 + wv];
    return make_float4(a.x, b.x, a.y, b.y);
}

// ============================================================
// Persistent fused kernel, grid 296 (single wave, occ 2 guaranteed).
// Phases per block: [norms/zero] -> conv rounds -> spin -> argmin.
// All FP chains identical to the previous versions (bit-exact).
// ============================================================
__global__ void __launch_bounds__(256, 2) k_fused(const float* __restrict__ zin,
                                                  const float* __restrict__ w,
                                                  const float* __restrict__ bias,
                                                  const float* __restrict__ emb,
                                                  float* __restrict__ out) {
    extern __shared__ __align__(16) char smem[];
    int tid = threadIdx.x;
    int blk = blockIdx.x;

    // ================= phase 0: norms / g_se / contrastive / sampled-zero =================
    if (blk < 8) {
        #pragma unroll
        for (int i = 0; i < 16; i++)
            out[SAMP_OFF + blk * 4096 + tid + 256 * i] = 0.0f;
    }
    if (blk < 32) {
        __shared__ float inv_n[32];
        __shared__ float sq[4][EDIM];
        if (tid < 32) {
            int i = blk * 32 + tid;
            float v = sumsq64_p((const float4*)(emb + (size_t)i * EDIM));
            g_se[i] = v;
            inv_n[tid] = 1.0f / sqrtf(v);
        }
        __syncthreads();
        int k = tid & 63, q = tid >> 6;
        float sacc = 0.f;
        #pragma unroll
        for (int i = 0; i < 8; i++) {
            int code = q * 8 + i;
            sacc += emb[(size_t)(blk * 32 + code) * EDIM + k] * inv_n[code];
        }
        sq[q][k] = sacc;
        __syncthreads();
        if (tid < EDIM)
            g_s_part[blk * EDIM + tid] =
                (sq[0][tid] + sq[1][tid]) + (sq[2][tid] + sq[3][tid]);
        __threadfence();
        __syncthreads();
        if (tid == 0) atomicAdd(&g_norm, 1);
    }

    // ================= phase 1: conv =================
    // unit u = b*32 + og*8 + pb: 128 threads, 128 pixels x 16 outputs.
    // rounds: u = r*592 + 2*blk + h (h = half). Covers u 0..1023 exactly.
    {
        unsigned long long* ws = (unsigned long long*)smem;   // [2][2048]
        float* bs = (float*)(ws + 4096);                      // [2][16]
        int h = tid >> 7, tc = tid & 127;

        #pragma unroll
        for (int r = 0; r < 2; r++) {
            int u = r * 592 + 2 * blk + h;
            bool valid = (u < 1024);
            int b = 0, og = 0, pb = 0;
            if (valid) {
                b = u >> 5; og = (u >> 3) & 3; pb = u & 7;
                int obase = og * 16;
                unsigned long long* wsh = ws + h * 2048;
                for (int m = tc; m < CIN * 8; m += 128) {
                    int c = m >> 3, uu = m & 7;
                    const float* wp = w + (size_t)(obase + 2 * uu) * CIN + c;
                    wsh[m] = pack2(wp[0], wp[CIN]);
                }
                if (tc < 16) bs[h * 16 + tc] = bias[obase + tc];
            }
            __syncthreads();
            if (valid) {
                int obase = og * 16;
                int p0 = pb * 128 + tc;
                const float* zp = zin + (size_t)b * CIN * HW + p0;

                unsigned long long acc[8];
                #pragma unroll
                for (int uu = 0; uu < 8; uu++) acc[uu] = 0ULL;

                float zn[8];
                #pragma unroll
                for (int i = 0; i < 8; i++) zn[i] = zp[(size_t)i * HW];

                const ulonglong2* ws2 = (const ulonglong2*)(ws + h * 2048);
                for (int ch = 0; ch < 32; ch++) {
                    float zc[8];
                    #pragma unroll
                    for (int i = 0; i < 8; i++) zc[i] = zn[i];
                    if (ch < 31) {
                        #pragma unroll
                        for (int i = 0; i < 8; i++)
                            zn[i] = zp[(size_t)((ch + 1) * 8 + i) * HW];
                    }
                    #pragma unroll
                    for (int cc = 0; cc < 8; cc++) {
                        int c = ch * 8 + cc;
                        unsigned long long zz = dupf(zc[cc]);
                        const ulonglong2* wrow = ws2 + c * 4;
                        #pragma unroll
                        for (int uu = 0; uu < 4; uu++) {
                            ulonglong2 wp = wrow[uu];
                            fma2(acc[2*uu],     zz, wp.x);
                            fma2(acc[2*uu + 1], zz, wp.y);
                        }
                    }
                }

                float* zo = g_z + (size_t)b * COUT * HW;
                #pragma unroll
                for (int uu = 0; uu < 8; uu++) {
                    int o = obase + 2 * uu;
                    float lo, hi;
                    unpack2(lo, hi, acc[uu]);
                    zo[(size_t)o * HW + p0]       = lo + bs[h*16 + 2*uu];
                    zo[(size_t)(o + 1) * HW + p0] = hi + bs[h*16 + 2*uu + 1];
                }
            }
            __threadfence();
            __syncthreads();
            if (valid && tc == 0) atomicAdd(&g_convdone[b], 1);
        }
    }

    // ================= phase 2: argmin =================
    if (blk >= NBLK) return;
    int ablk = blk;
    float4* zs4  = (float4*)smem;                  // [112][17]
    float4* es4  = zs4 + ZS_F4;                    // [2][64 pair-rows][33]
    float*  Sz_s = (float*)(es4 + 2 * ES_F4);      // [112]
    float*  se_s = Sz_s + ROWS_BLK;                // [2][128]
    float*  red  = se_s + 256;                     // [256]
    __shared__ int    is_last;
    __shared__ double rd[256];
    __shared__ float  sv[EDIM];

    int s   = tid & 15;
    int g   = tid >> 4;
    int row0 = ablk * ROWS_BLK;

    // spin until producers done: norms (g_se + sampled-zero) + own batches
    if (tid == 0) {
        int b0 = row0 / 1024;
        int last_row = row0 + ROWS_BLK - 1;
        if (last_row > NROWS - 1) last_row = NROWS - 1;
        int b1 = last_row / 1024;
        while (atomicAdd(&g_norm, 0) < 32) __nanosleep(64);
        while (atomicAdd(&g_convdone[b0], 0) < 32) __nanosleep(64);
        while (atomicAdd(&g_convdone[b1], 0) < 32) __nanosleep(64);
        __threadfence();
    }
    __syncthreads();

    // stage z rows (clamped for last block) + e tile 0 (gather) + se tile 0
    {
        const float4* zall = (const float4*)g_z;
        #pragma unroll
        for (int j = 0; j < RPT; j++) {
            int idx = tid + 256 * j;
            int r = idx >> 4, k4 = idx & 15;
            int grow = row0 + r;
            if (grow > NROWS - 1) grow = NROWS - 1;
            zs4[r * 17 + k4] = zall[(size_t)grow * 16 + k4];
        }
        #pragma unroll
        for (int j = 0; j < 8; j++) {
            int idx = tid + 256 * j;
            int pr = idx >> 5, wv = idx & 31;
            es4[pr * 33 + wv] = gather_e(emb, 0, idx);
        }
        if (tid < CODE_TILE) se_s[tid] = g_se[tid];
    }
    __syncthreads();
    if (tid < ROWS_BLK)
        Sz_s[tid] = sumsq64_p(zs4 + tid * 17);
    __syncthreads();

    float best[RPT];
    int   bi[RPT];
    #pragma unroll
    for (int i = 0; i < RPT; i++) { best[i] = 3.4e38f; bi[i] = 0; }

    const float2* zb = ((const float2*)zs4) + g * 34;
    const unsigned long long m2 = dupf(-2.0f);

    for (int t = 0; t < TILES; t++) {
        int cur = t & 1, nxt = 1 - cur;

        if (t + 1 < TILES) {
            #pragma unroll
            for (int j = 0; j < 8; j++) {
                int idx = tid + 256 * j;
                int pr = idx >> 5, wv = idx & 31;
                es4[nxt * ES_F4 + pr * 33 + wv] = gather_e(emb, t + 1, idx);
            }
            if (tid < CODE_TILE)
                se_s[nxt * 128 + tid] = g_se[(t + 1) * CODE_TILE + tid];
        }

        unsigned long long acc[RPT][4];
        #pragma unroll
        for (int i = 0; i < RPT; i++)
            #pragma unroll
            for (int q = 0; q < 4; q++) acc[i][q] = 0ULL;

        const ulonglong2* ebase = ((const ulonglong2*)(es4 + cur * ES_F4)) + s * 33;

        #pragma unroll 4
        for (int k4 = 0; k4 < 16; k4++) {
            unsigned long long zx[RPT], zy[RPT];
            // half A: dims 4k4, 4k4+1
            #pragma unroll
            for (int i = 0; i < RPT; i++) {
                float2 hh = zb[544 * i + 2 * k4];
                zx[i] = dupf(hh.x); zy[i] = dupf(hh.y);
            }
            #pragma unroll
            for (int q = 0; q < 4; q++) {
                ulonglong2 e01 = ebase[q * 528 + 2 * k4];
                #pragma unroll
                for (int i = 0; i < RPT; i++) {
                    fma2(acc[i][q], zx[i], e01.x);
                    fma2(acc[i][q], zy[i], e01.y);
                }
            }
            // half B: dims 4k4+2, 4k4+3
            #pragma unroll
            for (int i = 0; i < RPT; i++) {
                float2 hh = zb[544 * i + 2 * k4 + 1];
                zx[i] = dupf(hh.x); zy[i] = dupf(hh.y);
            }
            #pragma unroll
            for (int q = 0; q < 4; q++) {
                ulonglong2 e23 = ebase[q * 528 + 2 * k4 + 1];
                #pragma unroll
                for (int i = 0; i < RPT; i++) {
                    fma2(acc[i][q], zx[i], e23.x);
                    fma2(acc[i][q], zy[i], e23.y);
                }
            }
        }

        // eval (packed): per row, q ascending -> codes 8s+2q, 8s+2q+1 ascending
        #pragma unroll
        for (int i = 0; i < RPT; i++) {
            unsigned long long szd = dupf(Sz_s[g + 16 * i]);
            #pragma unroll
            for (int q = 0; q < 4; q++) {
                int jlo = 8 * s + 2 * q;
                unsigned long long se2 =
                    *(const unsigned long long*)(se_s + cur * 128 + jlo);
                unsigned long long d2 = add2(szd, se2);
                fma2(d2, m2, acc[i][q]);
                float dv, dw;
                unpack2(dv, dw, d2);
                if (dv < best[i]) { best[i] = dv; bi[i] = t * CODE_TILE + jlo; }
                if (dw < best[i]) { best[i] = dw; bi[i] = t * CODE_TILE + jlo + 1; }
            }
        }
        __syncthreads();
    }

    // lexicographic merge across the 16 sublanes (per row)
    unsigned m = 0xffffffffu;
    #pragma unroll
    for (int i = 0; i < RPT; i++) {
        float bv = best[i]; int bj = bi[i];
        #pragma unroll
        for (int off = 8; off > 0; off >>= 1) {
            float ob = __shfl_down_sync(m, bv, off, 16);
            int   oi = __shfl_down_sync(m, bj, off, 16);
            if (ob < bv || (ob == bv && oi < bj)) { bv = ob; bj = oi; }
        }
        bj = __shfl_sync(m, bj, 0, 16);
        bi[i] = bj;
    }

    // epilogue per valid row: idx/min_idx/scatter, z_q_st, loss partial
    float lacc = 0.f;
    #pragma unroll
    for (int i = 0; i < RPT; i++) {
        int rl = g + 16 * i;
        int row = row0 + rl;
        if (row < NROWS) {
            int bj = bi[i];
            if (s == 0) {
                g_idx[row] = bj;
                out[MIDX_OFF + row] = (float)bj;
                out[SAMP_OFF + bj] = 1.0f;
            }
            float4 e = ((const float4*)(emb + (size_t)bj * EDIM))[s];
            float4 z = zs4[rl * 17 + s];
            float dx = e.x - z.x, dy = e.y - z.y, dz = e.z - z.z, dw = e.w - z.w;
            float4 o;
            o.x = z.x + dx; o.y = z.y + dy; o.z = z.z + dz; o.w = z.w + dw;
            ((float4*)(out + ZQ_OFF + (size_t)row * EDIM))[s] = o;
            lacc += dx*dx + dy*dy + dz*dz + dw*dw;
        }
    }
    red[tid] = lacc;
    __syncthreads();
    #pragma unroll
    for (int st = 128; st > 0; st >>= 1) {
        if (tid < st) red[tid] += red[tid + st];
        __syncthreads();
    }
    if (tid == 0) {
        g_loss_part[ablk] = red[0];
        __threadfence();
        int old = atomicAdd(&g_done, 1);
        is_last = (old == NBLK - 1);
    }
    __syncthreads();

    // last argmin block: finalize loss + reset counters for next launch
    if (is_last) {
        __threadfence();
        double a = (double)g_loss_part[tid];
        if (tid + 256 < NBLK) a += (double)g_loss_part[tid + 256];
        rd[tid] = a;
        if (tid < EDIM) {
            float v = 0.f;
            #pragma unroll
            for (int j = 0; j < 32; j++) v += g_s_part[j * EDIM + tid];
            sv[tid] = v * v;
        }
        __syncthreads();
        #pragma unroll
        for (int st = 128; st > 0; st >>= 1) {
            if (tid < st) rd[tid] += rd[tid + st];
            __syncthreads();
        }
        if (tid == 0) {
            float c = 0.f;
            for (int j = 0; j < EDIM; j++) c += sv[j];
            out[LOSS_OFF] = (float)(1.25 * (rd[0] / (double)ZLEN))
                          + c / ((float)NE * (float)NE);
            g_done = 0;
            g_norm = 0;
        }
        if (tid < 32) g_convdone[tid] = 0;
    }
}

// ============================================================
extern "C" void kernel_launch(void* const* d_in, const int* in_sizes, int n_in,
                              void* d_out, int out_size) {
    const float* z_    = (const float*)d_in[0];
    const float* convw = (const float*)d_in[1];
    const float* convb = (const float*)d_in[2];
    const float* emb   = (const float*)d_in[3];
    float* out = (float*)d_out;

    cudaFuncSetAttribute(k_fused, cudaFuncAttributeMaxDynamicSharedMemorySize,
                         SMEM_FUSED);

    k_fused<<<GRID, 256, SMEM_FUSED>>>(z_, convw, convb, emb, out);
}

// round 17
// speedup vs baseline: 1.0992x; 1.0992x over previous
#include <cuda_runtime.h>
#include <math.h>

// ---------------- problem constants ----------------
#define BATCH   32
#define CIN     256
#define COUT    64
#define HW      1024
#define NE      1024
#define EDIM    64
#define NROWS   32768
#define ZLEN    (BATCH*COUT*HW)   // 2097152
#define TILES   8
#define CODE_TILE 128
#define ROWS_BLK 112
#define RPT      7
#define NCONV    256              // conv-role blocks (each = 2 old conv blocks)
#define NBLK     293              // argmin-role blocks
#define GRID     (NCONV + NBLK)   // 549

// output layout (concat, float32): z_q | loss | sampled | min_idx
#define ZQ_OFF   0
#define LOSS_OFF ((size_t)ZLEN)
#define SAMP_OFF ((size_t)ZLEN + 1)
#define MIDX_OFF ((size_t)ZLEN + 1 + NROWS)

// argmin smem: zs4[112*17] | es4[2][64*33] | Sz[112] | se[2][128] | red[256]
#define ZS_F4    (ROWS_BLK * 17)          // 1904
#define ES_F4    (64 * 33)                // 2112 per buffer
#define SMEM_FUSED ((ZS_F4 + 2*ES_F4) * 16 + ROWS_BLK * 4 + 256 * 4 + 256 * 4)

// ---------------- device scratch ----------------
__device__ __align__(16) float g_z[ZLEN];
__device__ __align__(16) float g_embi[NE * EDIM];   // pair-interleaved codebook
__device__ int   g_idx[NROWS];
__device__ float g_se[NE];
__device__ float g_loss_part[NBLK];
__device__ float g_s_part[32 * EDIM];
__device__ int   g_done;           // zero-init; reset by is_last each launch
__device__ int   g_convdone[32];   // zero-init; reset by is_last each launch

// ---------------- packed f32x2 helpers (bit-exact per-lane ops) ----------------
__device__ __forceinline__ unsigned long long dupf(float v) {
    unsigned long long r;
    asm("mov.b64 %0, {%1, %1};" : "=l"(r) : "r"(__float_as_uint(v)));
    return r;
}
__device__ __forceinline__ unsigned long long pack2(float a, float b) {
    unsigned long long r;
    asm("mov.b64 %0, {%1, %2};" : "=l"(r) : "r"(__float_as_uint(a)), "r"(__float_as_uint(b)));
    return r;
}
__device__ __forceinline__ void fma2(unsigned long long& d,
                                     unsigned long long a, unsigned long long b) {
    asm("fma.rn.f32x2 %0, %1, %2, %0;" : "+l"(d) : "l"(a), "l"(b));
}
__device__ __forceinline__ unsigned long long add2(unsigned long long a,
                                                   unsigned long long b) {
    unsigned long long d;
    asm("add.rn.f32x2 %0, %1, %2;" : "=l"(d) : "l"(a), "l"(b));
    return d;
}
__device__ __forceinline__ void unpack2(float& lo, float& hi, unsigned long long v) {
    asm("mov.b64 {%0, %1}, %2;" : "=f"(lo), "=f"(hi) : "l"(v));
}

// Replicated XLA-CPU reduce order: VF=4, IC=2, fmla, faddp-adjacent horizontal.
__device__ __forceinline__ float sumsq64_p(const float4* v4) {
    float a0=0.f,a1=0.f,a2=0.f,a3=0.f, b0=0.f,b1=0.f,b2=0.f,b3=0.f;
    #pragma unroll
    for (int t = 0; t < 8; t++) {
        float4 x = v4[2*t];
        a0 = __fmaf_rn(x.x, x.x, a0); a1 = __fmaf_rn(x.y, x.y, a1);
        a2 = __fmaf_rn(x.z, x.z, a2); a3 = __fmaf_rn(x.w, x.w, a3);
        float4 y = v4[2*t+1];
        b0 = __fmaf_rn(y.x, y.x, b0); b1 = __fmaf_rn(y.y, y.y, b1);
        b2 = __fmaf_rn(y.z, y.z, b2); b3 = __fmaf_rn(y.w, y.w, b3);
    }
    float L0 = a0 + b0, L1 = a1 + b1, L2 = a2 + b2, L3 = a3 + b3;
    return (L0 + L1) + (L2 + L3);
}

// Gather one float4 of the pair-interleaved e-tile straight from emb
// (used only for tile 0, staged before the producer spin).
__device__ __forceinline__ float4 gather_e(const float* __restrict__ emb,
                                           int tile, int idx) {
    int pr = idx >> 5, wv = idx & 31;
    int q = pr >> 4, sl = pr & 15;
    int jlo = tile * 128 + 8 * sl + 2 * q;
    const float2* e2 = (const float2*)emb;
    float2 a = e2[jlo * 32 + wv];
    float2 b = e2[(jlo + 1) * 32 + wv];
    return make_float4(a.x, b.x, a.y, b.y);
}

// ============================================================
// Fused kernel. blk < 256: conv role (2 old conv units in parallel
// halves; blocks 0-31 also do norms/contrastive + g_embi prep;
// blocks 0-7 zero 'sampled'); releases g_convdone[batch].
// blk >= 256: argmin role, stages e-tile 0 then spins on its batches.
// All FP chains identical to prior versions (bit-exact).
// ============================================================
__global__ void __launch_bounds__(256, 2) k_fused(const float* __restrict__ zin,
                                                  const float* __restrict__ w,
                                                  const float* __restrict__ bias,
                                                  const float* __restrict__ emb,
                                                  float* __restrict__ out) {
    extern __shared__ __align__(16) char smem[];
    int tid = threadIdx.x;
    int blk = blockIdx.x;

    if (blk < NCONV) {
        // ================= conv role =================
        unsigned long long* ws = (unsigned long long*)smem;   // [2][2048]
        float* bs = (float*)(ws + 4096);                      // [2][16]
        __shared__ float inv_n[32];
        __shared__ float sq[4][EDIM];

        int half = tid >> 7, tc = tid & 127;
        int co = 2 * blk + half;
        int b = co >> 4, quarter = (co >> 2) & 3, og = co & 3;
        int obase = og * 16;

        // zero 'sampled' region (blocks 0..7)
        if (blk < 8) {
            #pragma unroll
            for (int i = 0; i < 16; i++)
                out[SAMP_OFF + blk * 4096 + tid + 256 * i] = 0.0f;
        }

        // blocks 0..31 (batches 0..3): g_embi prep + norms + contrastive
        if (blk < 32) {
            // prep: pair-interleave codebook (2048 elements per block)
            #pragma unroll
            for (int e = 0; e < 8; e++) {
                int o = blk * 2048 + e * 256 + tid;
                int P = o >> 7, r = o & 127;
                int k = r >> 1, l = r & 1;
                int t = P >> 6, rem = P & 63;
                int q = rem >> 4, sl = rem & 15;
                int j = t * 128 + 8 * sl + 2 * q + l;
                g_embi[o] = emb[(size_t)j * EDIM + k];
            }
            if (blk == 0 && tid == 0) g_done = 0;

            if (tid < 32) {
                int i = blk * 32 + tid;
                float v = sumsq64_p((const float4*)(emb + (size_t)i * EDIM));
                g_se[i] = v;
                inv_n[tid] = 1.0f / sqrtf(v);
            }
            __syncthreads();
            int k = tid & 63, q = tid >> 6;       // q in 0..3
            float sacc = 0.f;
            #pragma unroll
            for (int i = 0; i < 8; i++) {
                int code = q * 8 + i;
                sacc += emb[(size_t)(blk * 32 + code) * EDIM + k] * inv_n[code];
            }
            sq[q][k] = sacc;
            __syncthreads();
            if (tid < EDIM)
                g_s_part[blk * EDIM + tid] =
                    (sq[0][tid] + sq[1][tid]) + (sq[2][tid] + sq[3][tid]);
        }

        // weights (each half loads its own 16KB)
        unsigned long long* wsh = ws + half * 2048;
        for (int m = tc; m < CIN * 8; m += 128) {
            int c = m >> 3, u = m & 7;
            const float* wp = w + (size_t)(obase + 2 * u) * CIN + c;
            wsh[m] = pack2(wp[0], wp[CIN]);
        }
        if (tc < 16) bs[half * 16 + tc] = bias[obase + tc];
        __syncthreads();

        int p0 = quarter * 256 + tc;
        const float* zp = zin + (size_t)b * CIN * HW + p0;

        unsigned long long acc[8][2];
        #pragma unroll
        for (int u = 0; u < 8; u++) { acc[u][0] = 0ULL; acc[u][1] = 0ULL; }

        float zn[2][8];
        #pragma unroll
        for (int j = 0; j < 2; j++)
            #pragma unroll
            for (int i = 0; i < 8; i++)
                zn[j][i] = zp[(size_t)i * HW + 128 * j];

        const ulonglong2* ws2 = (const ulonglong2*)wsh;
        for (int ch = 0; ch < 32; ch++) {
            float zc[2][8];
            #pragma unroll
            for (int j = 0; j < 2; j++)
                #pragma unroll
                for (int i = 0; i < 8; i++) zc[j][i] = zn[j][i];
            if (ch < 31) {
                #pragma unroll
                for (int j = 0; j < 2; j++)
                    #pragma unroll
                    for (int i = 0; i < 8; i++)
                        zn[j][i] = zp[(size_t)((ch + 1) * 8 + i) * HW + 128 * j];
            }
            #pragma unroll
            for (int cc = 0; cc < 8; cc++) {
                int c = ch * 8 + cc;
                unsigned long long zz0 = dupf(zc[0][cc]);
                unsigned long long zz1 = dupf(zc[1][cc]);
                const ulonglong2* wrow = ws2 + c * 4;
                #pragma unroll
                for (int uu = 0; uu < 4; uu++) {
                    ulonglong2 wp = wrow[uu];
                    fma2(acc[2*uu][0],     zz0, wp.x);
                    fma2(acc[2*uu][1],     zz1, wp.x);
                    fma2(acc[2*uu + 1][0], zz0, wp.y);
                    fma2(acc[2*uu + 1][1], zz1, wp.y);
                }
            }
        }

        float* zo = g_z + (size_t)b * COUT * HW;
        #pragma unroll
        for (int u = 0; u < 8; u++) {
            int o = obase + 2 * u;
            #pragma unroll
            for (int j = 0; j < 2; j++) {
                float lo, hi;
                unpack2(lo, hi, acc[u][j]);
                zo[(size_t)o * HW + p0 + 128 * j]       = lo + bs[half*16 + 2*u];
                zo[(size_t)(o + 1) * HW + p0 + 128 * j] = hi + bs[half*16 + 2*u + 1];
            }
        }

        // release: this batch's conv slice done (8 fused blocks per batch)
        __syncthreads();
        __threadfence();
        if (tid == 0) atomicAdd(&g_convdone[b], 1);
        return;
    }

    // ================= argmin role =================
    int ablk = blk - NCONV;
    float4* zs4  = (float4*)smem;                  // [112][17]
    float4* es4  = zs4 + ZS_F4;                    // [2][64 pair-rows][33]
    float*  Sz_s = (float*)(es4 + 2 * ES_F4);      // [112]
    float*  se_s = Sz_s + ROWS_BLK;                // [2][128]
    float*  red  = se_s + 256;                     // [256]
    __shared__ int    is_last;
    __shared__ double rd[256];
    __shared__ float  sv[EDIM];

    int s   = tid & 15;
    int g   = tid >> 4;
    int row0 = ablk * ROWS_BLK;

    // stage e tile 0 straight from emb (no producer needed) BEFORE spin
    #pragma unroll
    for (int j = 0; j < 8; j++) {
        int idx = tid + 256 * j;
        int pr = idx >> 5, wv = idx & 31;
        es4[pr * 33 + wv] = gather_e(emb, 0, idx);
    }

    // spin until producers done: batches 0..3 (norms/g_se/g_embi/zero)
    // + this block's own batch(es)
    if (tid == 0) {
        int b0 = row0 / 1024;
        int last_row = row0 + ROWS_BLK - 1;
        if (last_row > NROWS - 1) last_row = NROWS - 1;
        int b1 = last_row / 1024;
        #pragma unroll
        for (int bb = 0; bb < 4; bb++)
            while (atomicAdd(&g_convdone[bb], 0) < 8) __nanosleep(128);
        while (atomicAdd(&g_convdone[b0], 0) < 8) __nanosleep(128);
        while (atomicAdd(&g_convdone[b1], 0) < 8) __nanosleep(128);
        __threadfence();
    }
    __syncthreads();

    // stage z rows (clamped for last block) + se tile 0
    {
        const float4* zall = (const float4*)g_z;
        #pragma unroll
        for (int j = 0; j < RPT; j++) {
            int idx = tid + 256 * j;
            int r = idx >> 4, k4 = idx & 15;
            int grow = row0 + r;
            if (grow > NROWS - 1) grow = NROWS - 1;
            zs4[r * 17 + k4] = zall[(size_t)grow * 16 + k4];
        }
        if (tid < CODE_TILE) se_s[tid] = g_se[tid];
    }
    __syncthreads();
    if (tid < ROWS_BLK)
        Sz_s[tid] = sumsq64_p(zs4 + tid * 17);
    __syncthreads();

    float best[RPT];
    int   bi[RPT];
    #pragma unroll
    for (int i = 0; i < RPT; i++) { best[i] = 3.4e38f; bi[i] = 0; }

    const float4* gsrc = (const float4*)g_embi;
    const float2* zb = ((const float2*)zs4) + g * 34;
    const unsigned long long m2 = dupf(-2.0f);

    for (int t = 0; t < TILES; t++) {
        int cur = t & 1, nxt = 1 - cur;

        if (t + 1 < TILES) {
            const float4* src = gsrc + (size_t)(t + 1) * 2048;
            #pragma unroll
            for (int j = 0; j < 8; j++) {
                int idx = tid + 256 * j;
                int pr = idx >> 5, wv = idx & 31;
                es4[nxt * ES_F4 + pr * 33 + wv] = src[idx];
            }
            if (tid < CODE_TILE)
                se_s[nxt * 128 + tid] = g_se[(t + 1) * CODE_TILE + tid];
        }

        unsigned long long acc[RPT][4];
        #pragma unroll
        for (int i = 0; i < RPT; i++)
            #pragma unroll
            for (int q = 0; q < 4; q++) acc[i][q] = 0ULL;

        const ulonglong2* ebase = ((const ulonglong2*)(es4 + cur * ES_F4)) + s * 33;

        #pragma unroll 4
        for (int k4 = 0; k4 < 16; k4++) {
            unsigned long long zx[RPT], zy[RPT];
            // half A: dims 4k4, 4k4+1
            #pragma unroll
            for (int i = 0; i < RPT; i++) {
                float2 h = zb[544 * i + 2 * k4];
                zx[i] = dupf(h.x); zy[i] = dupf(h.y);
            }
            #pragma unroll
            for (int q = 0; q < 4; q++) {
                ulonglong2 e01 = ebase[q * 528 + 2 * k4];
                #pragma unroll
                for (int i = 0; i < RPT; i++) {
                    fma2(acc[i][q], zx[i], e01.x);
                    fma2(acc[i][q], zy[i], e01.y);
                }
            }
            // half B: dims 4k4+2, 4k4+3
            #pragma unroll
            for (int i = 0; i < RPT; i++) {
                float2 h = zb[544 * i + 2 * k4 + 1];
                zx[i] = dupf(h.x); zy[i] = dupf(h.y);
            }
            #pragma unroll
            for (int q = 0; q < 4; q++) {
                ulonglong2 e23 = ebase[q * 528 + 2 * k4 + 1];
                #pragma unroll
                for (int i = 0; i < RPT; i++) {
                    fma2(acc[i][q], zx[i], e23.x);
                    fma2(acc[i][q], zy[i], e23.y);
                }
            }
        }

        // eval (packed): per row, q ascending -> codes 8s+2q, 8s+2q+1 ascending
        #pragma unroll
        for (int i = 0; i < RPT; i++) {
            unsigned long long szd = dupf(Sz_s[g + 16 * i]);
            #pragma unroll
            for (int q = 0; q < 4; q++) {
                int jlo = 8 * s + 2 * q;
                unsigned long long se2 =
                    *(const unsigned long long*)(se_s + cur * 128 + jlo);
                unsigned long long d2 = add2(szd, se2);
                fma2(d2, m2, acc[i][q]);
                float dv, dw;
                unpack2(dv, dw, d2);
                if (dv < best[i]) { best[i] = dv; bi[i] = t * CODE_TILE + jlo; }
                if (dw < best[i]) { best[i] = dw; bi[i] = t * CODE_TILE + jlo + 1; }
            }
        }
        __syncthreads();
    }

    // lexicographic merge across the 16 sublanes (per row)
    unsigned m = 0xffffffffu;
    #pragma unroll
    for (int i = 0; i < RPT; i++) {
        float bv = best[i]; int bj = bi[i];
        #pragma unroll
        for (int off = 8; off > 0; off >>= 1) {
            float ob = __shfl_down_sync(m, bv, off, 16);
            int   oi = __shfl_down_sync(m, bj, off, 16);
            if (ob < bv || (ob == bv && oi < bj)) { bv = ob; bj = oi; }
        }
        bj = __shfl_sync(m, bj, 0, 16);
        bi[i] = bj;
    }

    // epilogue per valid row: idx/min_idx/scatter, z_q_st, loss partial
    float lacc = 0.f;
    #pragma unroll
    for (int i = 0; i < RPT; i++) {
        int rl = g + 16 * i;
        int row = row0 + rl;
        if (row < NROWS) {
            int bj = bi[i];
            if (s == 0) {
                g_idx[row] = bj;
                out[MIDX_OFF + row] = (float)bj;
                out[SAMP_OFF + bj] = 1.0f;
            }
            float4 e = ((const float4*)(emb + (size_t)bj * EDIM))[s];
            float4 z = zs4[rl * 17 + s];
            float dx = e.x - z.x, dy = e.y - z.y, dz = e.z - z.z, dw = e.w - z.w;
            float4 o;
            o.x = z.x + dx; o.y = z.y + dy; o.z = z.z + dz; o.w = z.w + dw;
            ((float4*)(out + ZQ_OFF + (size_t)row * EDIM))[s] = o;
            lacc += dx*dx + dy*dy + dz*dz + dw*dw;
        }
    }
    red[tid] = lacc;
    __syncthreads();
    #pragma unroll
    for (int st = 128; st > 0; st >>= 1) {
        if (tid < st) red[tid] += red[tid + st];
        __syncthreads();
    }
    if (tid == 0) {
        g_loss_part[ablk] = red[0];
        __threadfence();
        int old = atomicAdd(&g_done, 1);
        is_last = (old == NBLK - 1);
    }
    __syncthreads();

    // last argmin block: finalize loss + reset counters for next launch
    if (is_last) {
        __threadfence();
        double a = (double)g_loss_part[tid];
        if (tid + 256 < NBLK) a += (double)g_loss_part[tid + 256];
        rd[tid] = a;
        if (tid < EDIM) {
            float v = 0.f;
            #pragma unroll
            for (int j = 0; j < 32; j++) v += g_s_part[j * EDIM + tid];
            sv[tid] = v * v;
        }
        __syncthreads();
        #pragma unroll
        for (int st = 128; st > 0; st >>= 1) {
            if (tid < st) rd[tid] += rd[tid + st];
            __syncthreads();
        }
        if (tid == 0) {
            float c = 0.f;
            for (int j = 0; j < EDIM; j++) c += sv[j];
            out[LOSS_OFF] = (float)(1.25 * (rd[0] / (double)ZLEN))
                          + c / ((float)NE * (float)NE);
            g_done = 0;
        }
        if (tid < 32) g_convdone[tid] = 0;
    }
}

// ============================================================
extern "C" void kernel_launch(void* const* d_in, const int* in_sizes, int n_in,
                              void* d_out, int out_size) {
    const float* z_    = (const float*)d_in[0];
    const float* convw = (const float*)d_in[1];
    const float* convb = (const float*)d_in[2];
    const float* emb   = (const float*)d_in[3];
    float* out = (float*)d_out;

    cudaFuncSetAttribute(k_fused, cudaFuncAttributeMaxDynamicSharedMemorySize,
                         SMEM_FUSED);

    k_fused<<<GRID, 256, SMEM_FUSED>>>(z_, convw, convb, emb, out);
}